// round 13
// baseline (speedup 1.0000x reference)
#include <cuda_runtime.h>
#include <cuda_bf16.h>
#include <math.h>
#include <stdint.h>

#define NN 50000
#define EE 800000

// ---------------- scratch (device globals; no allocation) ----------------
__device__ __align__(256) float g_bufA[NN * 128];   // GEMM output h
__device__ __align__(256) float g_bufB[NN * 128];   // layer output (post agg/ELU)
__device__ __align__(256) float g_zraw[NN * 16];
__device__ __align__(256) float g_als[NN * 8];
__device__ __align__(256) float g_ald[NN * 8];
__device__ int g_deg[NN];
__device__ int g_incl[NN];
__device__ int g_rowptr[NN + 1];
__device__ int g_cursor[NN];
__device__ int g_colsrc[EE];
__device__ int g_bsums[64];
__device__ int g_boffs[64];

// ---------------- CSR build (edge_index is int32: [2, E]) ----------------
__global__ void k_zero_deg(int n) {
    int i = blockIdx.x * blockDim.x + threadIdx.x;
    if (i < n) g_deg[i] = 0;
}

__global__ void k_count(const int* __restrict__ ei, int E) {
    int e = blockIdx.x * blockDim.x + threadIdx.x;
    if (e < E) {
        int dst = ei[E + e];
        if ((unsigned)dst < (unsigned)NN) atomicAdd(&g_deg[dst], 1);
    }
}

__global__ void k_scan1(int n) {
    int tid = threadIdx.x;
    int gid = blockIdx.x * 1024 + tid;
    int v = (gid < n) ? g_deg[gid] : 0;
    int lane = tid & 31, wid = tid >> 5;
    int x = v;
    #pragma unroll
    for (int off = 1; off < 32; off <<= 1) {
        int y = __shfl_up_sync(0xffffffffu, x, off);
        if (lane >= off) x += y;
    }
    __shared__ int ws[32];
    if (lane == 31) ws[wid] = x;
    __syncthreads();
    if (wid == 0) {
        int t = ws[lane];
        #pragma unroll
        for (int off = 1; off < 32; off <<= 1) {
            int y = __shfl_up_sync(0xffffffffu, t, off);
            if (lane >= off) t += y;
        }
        ws[lane] = t;
    }
    __syncthreads();
    int add = (wid > 0) ? ws[wid - 1] : 0;
    x += add;
    if (gid < n) g_incl[gid] = x;
    if (tid == 1023) g_bsums[blockIdx.x] = x;
}

__global__ void k_scan2(int nb) {
    if (threadIdx.x == 0 && blockIdx.x == 0) {
        int s = 0;
        for (int i = 0; i < nb; i++) {
            int t = g_bsums[i];
            g_boffs[i] = s;
            s += t;
        }
    }
}

__global__ void k_scan3(int n, int E) {
    int gid = blockIdx.x * blockDim.x + threadIdx.x;
    if (gid < n) {
        int b = gid >> 10;
        int excl = g_incl[gid] - g_deg[gid] + g_boffs[b];
        g_rowptr[gid] = excl;
        g_cursor[gid] = excl;
    }
    if (gid == 0) g_rowptr[n] = E;
}

__global__ void k_fill(const int* __restrict__ ei, int E) {
    int e = blockIdx.x * blockDim.x + threadIdx.x;
    if (e < E) {
        int src = ei[e];
        int dst = ei[E + e];
        if ((unsigned)dst < (unsigned)NN && (unsigned)src < (unsigned)NN) {
            int pos = atomicAdd(&g_cursor[dst], 1);
            g_colsrc[pos] = src;
        }
    }
}

// ---------------- helpers ----------------
__device__ __forceinline__ void cp_async16(void* smem_dst, const void* gsrc, int src_bytes) {
    uint32_t saddr = (uint32_t)__cvta_generic_to_shared(smem_dst);
    asm volatile("cp.async.cg.shared.global [%0], [%1], 16, %2;\n"
                 :: "r"(saddr), "l"(gsrc), "r"(src_bytes));
}

__device__ __forceinline__ void split_pack(float x0, float x1, uint32_t& hi, uint32_t& lo) {
    __nv_bfloat16 h0 = __float2bfloat16(x0);
    __nv_bfloat16 h1 = __float2bfloat16(x1);
    __nv_bfloat16 l0 = __float2bfloat16(x0 - __bfloat162float(h0));
    __nv_bfloat16 l1 = __float2bfloat16(x1 - __bfloat162float(h1));
    hi = ((uint32_t)__bfloat16_as_ushort(h1) << 16) | (uint32_t)__bfloat16_as_ushort(h0);
    lo = ((uint32_t)__bfloat16_as_ushort(l1) << 16) | (uint32_t)__bfloat16_as_ushort(l0);
}

__device__ __forceinline__ void mma16816(float c[4], const uint32_t a[4], const uint32_t b[2]) {
    asm volatile(
        "mma.sync.aligned.m16n8k16.row.col.f32.bf16.bf16.f32 "
        "{%0,%1,%2,%3}, {%4,%5,%6,%7}, {%8,%9}, {%0,%1,%2,%3};"
        : "+f"(c[0]), "+f"(c[1]), "+f"(c[2]), "+f"(c[3])
        : "r"(a[0]), "r"(a[1]), "r"(a[2]), "r"(a[3]), "r"(b[0]), "r"(b[1]));
}

// ---------------- tensor-core GEMM: g_bufA[M,128] = A[M,K] * B[K,128] ----------------
#define LDA 20
#define LDB 132
__global__ __launch_bounds__(256) void mma_gemm128(const float* __restrict__ Aext,
                                                   const float* __restrict__ B,
                                                   int M, int K, int useExt) {
    const float* A = useExt ? Aext : (const float*)g_bufB;
    float* C = g_bufA;
    __shared__ float sA[2][128 * LDA];
    __shared__ float sB[2][16 * LDB];

    int tid = threadIdx.x;
    int wid = tid >> 5, lane = tid & 31;
    int g = lane >> 2, tg = lane & 3;
    int warp_m = wid >> 2;
    int warp_n = wid & 3;
    int block_row = blockIdx.x * 128;

    float acc[4][4][4];
    #pragma unroll
    for (int mi = 0; mi < 4; mi++)
        #pragma unroll
        for (int ni = 0; ni < 4; ni++)
            #pragma unroll
            for (int q = 0; q < 4; q++) acc[mi][ni][q] = 0.f;

    int nsteps = (K + 15) >> 4;

    auto load_stage = [&](int s) {
        int buf = s & 1;
        int k0 = s << 4;
        #pragma unroll
        for (int q = 0; q < 2; q++) {
            int c = tid + q * 256;
            int r = c >> 2;
            int cq = (c & 3) << 2;
            int grow = block_row + r;
            if (grow >= M) grow = M - 1;
            int kc = k0 + cq;
            int bytes = (K - kc) * 4;
            bytes = bytes < 0 ? 0 : (bytes > 16 ? 16 : bytes);
            int kcc = kc > K - 4 ? K - 4 : kc;
            cp_async16(&sA[buf][r * LDA + cq], &A[(size_t)grow * K + kcc], bytes);
        }
        #pragma unroll
        for (int q = 0; q < 2; q++) {
            int c = tid + q * 256;
            int kk = c >> 5;
            int c0 = (c & 31) << 2;
            int gk = k0 + kk;
            int bytes = gk < K ? 16 : 0;
            if (gk > K - 1) gk = K - 1;
            cp_async16(&sB[buf][kk * LDB + c0], &B[(size_t)gk * 128 + c0], bytes);
        }
    };

    load_stage(0);
    asm volatile("cp.async.commit_group;\n");

    for (int s = 0; s < nsteps; s++) {
        if (s + 1 < nsteps) {
            load_stage(s + 1);
            asm volatile("cp.async.commit_group;\n");
            asm volatile("cp.async.wait_group 1;\n");
        } else {
            asm volatile("cp.async.wait_group 0;\n");
        }
        __syncthreads();

        int buf = s & 1;
        const float* Ar = sA[buf];
        const float* Br = sB[buf];

        uint32_t ah[4][4], al[4][4], bh[4][2], bl[4][2];
        #pragma unroll
        for (int mi = 0; mi < 4; mi++) {
            int r0 = warp_m * 64 + mi * 16 + g;
            float2 p0 = *(const float2*)&Ar[r0 * LDA + 2 * tg];
            float2 p1 = *(const float2*)&Ar[(r0 + 8) * LDA + 2 * tg];
            float2 p2 = *(const float2*)&Ar[r0 * LDA + 2 * tg + 8];
            float2 p3 = *(const float2*)&Ar[(r0 + 8) * LDA + 2 * tg + 8];
            split_pack(p0.x, p0.y, ah[mi][0], al[mi][0]);
            split_pack(p1.x, p1.y, ah[mi][1], al[mi][1]);
            split_pack(p2.x, p2.y, ah[mi][2], al[mi][2]);
            split_pack(p3.x, p3.y, ah[mi][3], al[mi][3]);
        }
        #pragma unroll
        for (int ni = 0; ni < 4; ni++) {
            int col = warp_n * 32 + ni * 8 + g;
            split_pack(Br[(2 * tg) * LDB + col], Br[(2 * tg + 1) * LDB + col],
                       bh[ni][0], bl[ni][0]);
            split_pack(Br[(2 * tg + 8) * LDB + col], Br[(2 * tg + 9) * LDB + col],
                       bh[ni][1], bl[ni][1]);
        }
        #pragma unroll
        for (int mi = 0; mi < 4; mi++)
            #pragma unroll
            for (int ni = 0; ni < 4; ni++) {
                mma16816(acc[mi][ni], ah[mi], bh[ni]);
                mma16816(acc[mi][ni], ah[mi], bl[ni]);
                mma16816(acc[mi][ni], al[mi], bh[ni]);
            }
        __syncthreads();
    }

    #pragma unroll
    for (int mi = 0; mi < 4; mi++) {
        #pragma unroll
        for (int ni = 0; ni < 4; ni++) {
            int row = block_row + warp_m * 64 + mi * 16 + g;
            int col = warp_n * 32 + ni * 8 + 2 * tg;
            if (row < M)
                *(float2*)&C[(size_t)row * 128 + col] = make_float2(acc[mi][ni][0], acc[mi][ni][1]);
            if (row + 8 < M)
                *(float2*)&C[(size_t)(row + 8) * 128 + col] = make_float2(acc[mi][ni][2], acc[mi][ni][3]);
        }
    }
}

// ---------------- SGEMM: g_zraw[M,16] = g_bufB[M,128] * W[128,16] ----------------
__global__ __launch_bounds__(256) void sgemm16(const float* __restrict__ W, int M) {
    const float* A = g_bufB;
    float* C = g_zraw;
    __shared__ float Ws[128][16];
    __shared__ float xs[16][128];
    int tid = threadIdx.x;
    {
        int base = tid * 8;
        #pragma unroll
        for (int q = 0; q < 2; q++) {
            float4 v = *(const float4*)&W[base + q * 4];
            int o = base + q * 4;
            Ws[(o + 0) >> 4][(o + 0) & 15] = v.x;
            Ws[(o + 1) >> 4][(o + 1) & 15] = v.y;
            Ws[(o + 2) >> 4][(o + 2) & 15] = v.z;
            Ws[(o + 3) >> 4][(o + 3) & 15] = v.w;
        }
    }
    int row0 = blockIdx.x * 16;
    {
        #pragma unroll
        for (int q = 0; q < 2; q++) {
            int idx = tid * 2 + q;
            int r = idx >> 5;
            int c4 = (idx & 31) * 4;
            float4 v = make_float4(0.f, 0.f, 0.f, 0.f);
            if (row0 + r < M) v = *(const float4*)&A[(size_t)(row0 + r) * 128 + c4];
            *(float4*)&xs[r][c4] = v;
        }
    }
    __syncthreads();
    int r = tid >> 4;
    int c = tid & 15;
    float acc = 0.f;
    #pragma unroll 8
    for (int k = 0; k < 128; k++) acc += xs[r][k] * Ws[k][c];
    int row = row0 + r;
    if (row < M) C[(size_t)row * 16 + c] = acc;
}

// ---------------- per-node attention coefficients ----------------
__global__ void compute_al(const float* __restrict__ asrc,
                           const float* __restrict__ adst, int n, int H, int which) {
    int idx = blockIdx.x * blockDim.x + threadIdx.x;
    if (idx >= n * H) return;
    int head = idx % H;
    int node = idx / H;
    const float* h = (which == 0) ? (const float*)g_bufA : (const float*)g_zraw;
    const float* hp = h + (size_t)node * H * 16 + head * 16;
    const float* as = asrc + head * 16;
    const float* ad = adst + head * 16;
    float s = 0.f, d = 0.f;
    #pragma unroll
    for (int c = 0; c < 16; c++) {
        float v = hp[c];
        s += v * as[c];
        d += v * ad[c];
    }
    g_als[idx] = s;
    g_ald[idx] = d;
}

// ---------------- fused softmax + aggregate + bias + ELU, C=128 H=8 ----------------
// One warp per node, 256 threads, no smem. Max-free softmax.
// Pass A: denom gather. Pass B: weighted aggregate, unrolled x2 for MLP.
__global__ __launch_bounds__(256) void gat_agg128(const float* __restrict__ bias, int n) {
    const float* h = g_bufA;
    float* out = g_bufB;
    int warp = (blockIdx.x * blockDim.x + threadIdx.x) >> 5;
    int lane = threadIdx.x & 31;
    if (warp >= n) return;
    int start = g_rowptr[warp];
    int end = g_rowptr[warp + 1];
    int myhead = lane >> 2;

    float4 a0 = *(const float4*)&g_ald[warp * 8];
    float4 a1 = *(const float4*)&g_ald[warp * 8 + 4];
    float aldv[8] = {a0.x, a0.y, a0.z, a0.w, a1.x, a1.y, a1.z, a1.w};

    // ---- pass A: per-head denominator (plain exp, no max) ----
    float dsum[8];
    #pragma unroll
    for (int i = 0; i < 8; i++) dsum[i] = 0.f;
    for (int e = start + lane; e < end; e += 32) {
        int s = g_colsrc[e];
        float4 s0 = *(const float4*)&g_als[s * 8];
        float4 s1 = *(const float4*)&g_als[s * 8 + 4];
        float lg[8] = {s0.x + aldv[0], s0.y + aldv[1], s0.z + aldv[2], s0.w + aldv[3],
                       s1.x + aldv[4], s1.y + aldv[5], s1.z + aldv[6], s1.w + aldv[7]};
        #pragma unroll
        for (int hh = 0; hh < 8; hh++) {
            float l = lg[hh];
            l = l > 0.f ? l : 0.2f * l;
            dsum[hh] += __expf(l);
        }
    }
    #pragma unroll
    for (int hh = 0; hh < 8; hh++)
        #pragma unroll
        for (int off = 16; off > 0; off >>= 1)
            dsum[hh] += __shfl_xor_sync(0xffffffffu, dsum[hh], off);

    float invd = 1.0f / (dsum[myhead] + 1e-16f);
    float aldh = aldv[myhead];

    // ---- pass B: weighted aggregation, 2 edges in flight ----
    float4 acc = make_float4(0.f, 0.f, 0.f, 0.f);
    int e = start;
    for (; e + 2 <= end; e += 2) {
        int s0 = g_colsrc[e];
        int s1 = g_colsrc[e + 1];
        float l0 = g_als[s0 * 8 + myhead] + aldh;
        float l1 = g_als[s1 * 8 + myhead] + aldh;
        float4 v0 = *(const float4*)&h[(size_t)s0 * 128 + lane * 4];
        float4 v1 = *(const float4*)&h[(size_t)s1 * 128 + lane * 4];
        l0 = l0 > 0.f ? l0 : 0.2f * l0;
        l1 = l1 > 0.f ? l1 : 0.2f * l1;
        float al0 = __expf(l0) * invd;
        float al1 = __expf(l1) * invd;
        acc.x += al0 * v0.x + al1 * v1.x;
        acc.y += al0 * v0.y + al1 * v1.y;
        acc.z += al0 * v0.z + al1 * v1.z;
        acc.w += al0 * v0.w + al1 * v1.w;
    }
    if (e < end) {
        int s = g_colsrc[e];
        float l = g_als[s * 8 + myhead] + aldh;
        l = l > 0.f ? l : 0.2f * l;
        float alpha = __expf(l) * invd;
        float4 v = *(const float4*)&h[(size_t)s * 128 + lane * 4];
        acc.x += alpha * v.x;
        acc.y += alpha * v.y;
        acc.z += alpha * v.z;
        acc.w += alpha * v.w;
    }
    float4 bv = *(const float4*)&bias[lane * 4];
    float4 o;
    o.x = acc.x + bv.x;
    o.y = acc.y + bv.y;
    o.z = acc.z + bv.z;
    o.w = acc.w + bv.w;
    o.x = o.x > 0.f ? o.x : expm1f(o.x);
    o.y = o.y > 0.f ? o.y : expm1f(o.y);
    o.z = o.z > 0.f ? o.z : expm1f(o.z);
    o.w = o.w > 0.f ? o.w : expm1f(o.w);
    *(float4*)&out[(size_t)warp * 128 + lane * 4] = o;
}

// ---------------- fused softmax + aggregate + bias, C=16 H=1 (layer 2) ----------------
__global__ __launch_bounds__(256) void gat_agg16(const float* __restrict__ bias,
                                                 float* __restrict__ out, int n) {
    const float* h = g_zraw;
    int warp = (blockIdx.x * blockDim.x + threadIdx.x) >> 5;
    int lane = threadIdx.x & 31;
    if (warp >= n) return;
    int start = g_rowptr[warp];
    int end = g_rowptr[warp + 1];
    float aldv = g_ald[warp];

    float dsum = 0.f;
    for (int e = start + lane; e < end; e += 32) {
        int s = g_colsrc[e];
        float l = g_als[s] + aldv;
        l = l > 0.f ? l : 0.2f * l;
        dsum += __expf(l);
    }
    #pragma unroll
    for (int off = 16; off > 0; off >>= 1)
        dsum += __shfl_xor_sync(0xffffffffu, dsum, off);
    float invd = 1.0f / (dsum + 1e-16f);

    float acc = 0.f;
    for (int e = start; e < end; e++) {
        int s = g_colsrc[e];
        float l = g_als[s] + aldv;
        l = l > 0.f ? l : 0.2f * l;
        float alpha = __expf(l) * invd;
        if (lane < 16) acc += alpha * h[(size_t)s * 16 + lane];
    }
    if (lane < 16) out[(size_t)warp * 16 + lane] = acc + bias[lane];
}

// ---------------- host launch ----------------
extern "C" void kernel_launch(void* const* d_in, const int* in_sizes, int n_in,
                              void* d_out, int out_size) {
    const float* x = (const float*)d_in[0];
    const int* ei = (const int*)d_in[1];
    const float* W0 = (const float*)d_in[2];
    const float* as0 = (const float*)d_in[3];
    const float* ad0 = (const float*)d_in[4];
    const float* b0 = (const float*)d_in[5];
    const float* W1 = (const float*)d_in[6];
    const float* as1 = (const float*)d_in[7];
    const float* ad1 = (const float*)d_in[8];
    const float* b1 = (const float*)d_in[9];
    const float* W2 = (const float*)d_in[10];
    const float* as2 = (const float*)d_in[11];
    const float* ad2 = (const float*)d_in[12];
    const float* b2 = (const float*)d_in[13];
    float* out = (float*)d_out;

    const int n = NN;
    const int E = EE;
    const int G = 1000;

    // CSR build interleaved with layer-0 GEMM. The GEMM depends only on x/W0,
    // so it is placed at launch index 3 — the slot the ncu capture window hits —
    // to finally get a profile of the heavy kernel. CSR ordering is preserved.
    k_zero_deg<<<(n + 255) / 256, 256>>>(n);
    k_count<<<(E + 255) / 256, 256>>>(ei, E);
    int nb = (n + 1023) / 1024;
    k_scan1<<<nb, 1024>>>(n);
    mma_gemm128<<<(n + 127) / 128, 256>>>(x, W0, n, G, 1);   // layer-0 GEMM (index 3)
    k_scan2<<<1, 32>>>(nb);
    k_scan3<<<(n + 255) / 256, 256>>>(n, E);
    k_fill<<<(E + 255) / 256, 256>>>(ei, E);

    // layer 0 (GEMM already issued above)
    compute_al<<<(n * 8 + 255) / 256, 256>>>(as0, ad0, n, 8, 0);
    gat_agg128<<<(n * 32 + 255) / 256, 256>>>(b0, n);

    // layer 1
    mma_gemm128<<<(n + 127) / 128, 256>>>(nullptr, W1, n, 128, 0);
    compute_al<<<(n * 8 + 255) / 256, 256>>>(as1, ad1, n, 8, 0);
    gat_agg128<<<(n * 32 + 255) / 256, 256>>>(b1, n);

    // layer 2
    sgemm16<<<(n + 15) / 16, 256>>>(W2, n);
    compute_al<<<(n + 255) / 256, 256>>>(as2, ad2, n, 1, 1);
    gat_agg16<<<(n * 32 + 255) / 256, 256>>>(b2, out, n);
}

// round 14
// speedup vs baseline: 1.1551x; 1.1551x over previous
#include <cuda_runtime.h>
#include <cuda_bf16.h>
#include <math.h>
#include <stdint.h>

#define NN 50000
#define EE 800000

// ---------------- scratch (device globals; no allocation) ----------------
__device__ __align__(256) float g_bufA[NN * 128];   // GEMM output h
__device__ __align__(256) float g_bufB[NN * 128];   // layer output (post agg/ELU)
__device__ __align__(256) float g_zraw[NN * 16];
__device__ __align__(256) float g_als[NN * 8];
__device__ __align__(256) float g_ald[NN * 8];
__device__ int g_deg[NN];
__device__ int g_incl[NN];
__device__ int g_rowptr[NN + 1];
__device__ int g_cursor[NN];
__device__ int g_colsrc[EE];
__device__ int g_bsums[64];
__device__ int g_boffs[64];

// ---------------- CSR build (edge_index is int32: [2, E]) ----------------
__global__ void k_zero_deg(int n) {
    int i = blockIdx.x * blockDim.x + threadIdx.x;
    if (i < n) g_deg[i] = 0;
}

__global__ void k_count(const int* __restrict__ ei, int E) {
    int e = blockIdx.x * blockDim.x + threadIdx.x;
    if (e < E) {
        int dst = ei[E + e];
        if ((unsigned)dst < (unsigned)NN) atomicAdd(&g_deg[dst], 1);
    }
}

__global__ void k_scan1(int n) {
    int tid = threadIdx.x;
    int gid = blockIdx.x * 1024 + tid;
    int v = (gid < n) ? g_deg[gid] : 0;
    int lane = tid & 31, wid = tid >> 5;
    int x = v;
    #pragma unroll
    for (int off = 1; off < 32; off <<= 1) {
        int y = __shfl_up_sync(0xffffffffu, x, off);
        if (lane >= off) x += y;
    }
    __shared__ int ws[32];
    if (lane == 31) ws[wid] = x;
    __syncthreads();
    if (wid == 0) {
        int t = ws[lane];
        #pragma unroll
        for (int off = 1; off < 32; off <<= 1) {
            int y = __shfl_up_sync(0xffffffffu, t, off);
            if (lane >= off) t += y;
        }
        ws[lane] = t;
    }
    __syncthreads();
    int add = (wid > 0) ? ws[wid - 1] : 0;
    x += add;
    if (gid < n) g_incl[gid] = x;
    if (tid == 1023) g_bsums[blockIdx.x] = x;
}

__global__ void k_scan2(int nb) {
    if (threadIdx.x == 0 && blockIdx.x == 0) {
        int s = 0;
        for (int i = 0; i < nb; i++) {
            int t = g_bsums[i];
            g_boffs[i] = s;
            s += t;
        }
    }
}

__global__ void k_scan3(int n, int E) {
    int gid = blockIdx.x * blockDim.x + threadIdx.x;
    if (gid < n) {
        int b = gid >> 10;
        int excl = g_incl[gid] - g_deg[gid] + g_boffs[b];
        g_rowptr[gid] = excl;
        g_cursor[gid] = excl;
    }
    if (gid == 0) g_rowptr[n] = E;
}

__global__ void k_fill(const int* __restrict__ ei, int E) {
    int e = blockIdx.x * blockDim.x + threadIdx.x;
    if (e < E) {
        int src = ei[e];
        int dst = ei[E + e];
        if ((unsigned)dst < (unsigned)NN && (unsigned)src < (unsigned)NN) {
            int pos = atomicAdd(&g_cursor[dst], 1);
            g_colsrc[pos] = src;
        }
    }
}

// ---------------- helpers ----------------
__device__ __forceinline__ void cp_async16(void* smem_dst, const void* gsrc, int src_bytes) {
    uint32_t saddr = (uint32_t)__cvta_generic_to_shared(smem_dst);
    asm volatile("cp.async.cg.shared.global [%0], [%1], 16, %2;\n"
                 :: "r"(saddr), "l"(gsrc), "r"(src_bytes));
}

// hi/lo split of two fp32 values into packed bf16x2 words, using packed
// conversion intrinsics (1 F2FP for hi pair, 1 for lo pair).
__device__ __forceinline__ void split_pack(float x0, float x1, uint32_t& hi, uint32_t& lo) {
    __nv_bfloat162 h2 = __floats2bfloat162_rn(x0, x1);   // .x=bf16(x0) low, .y=bf16(x1) high
    hi = *reinterpret_cast<uint32_t*>(&h2);
    float r0 = x0 - __bfloat162float(h2.x);
    float r1 = x1 - __bfloat162float(h2.y);
    __nv_bfloat162 l2 = __floats2bfloat162_rn(r0, r1);
    lo = *reinterpret_cast<uint32_t*>(&l2);
}

__device__ __forceinline__ void mma16816(float c[4], const uint32_t a[4], const uint32_t b[2]) {
    asm volatile(
        "mma.sync.aligned.m16n8k16.row.col.f32.bf16.bf16.f32 "
        "{%0,%1,%2,%3}, {%4,%5,%6,%7}, {%8,%9}, {%0,%1,%2,%3};"
        : "+f"(c[0]), "+f"(c[1]), "+f"(c[2]), "+f"(c[3])
        : "r"(a[0]), "r"(a[1]), "r"(a[2]), "r"(a[3]), "r"(b[0]), "r"(b[1]));
}

// ---------------- tensor-core GEMM: g_bufA[M,128] = A[M,K] * B[K,128] ----------------
// bf16 hi/lo split (3-MMA), cp.async 2-stage pipeline with ONE barrier per k-step:
// wait -> barrier -> issue next cp.async -> compute. The post-barrier issue is
// ordered after all of the previous iteration's reads of the target buffer, so
// the old trailing barrier is redundant.
#define LDA 20
#define LDB 132
__global__ __launch_bounds__(256) void mma_gemm128(const float* __restrict__ Aext,
                                                   const float* __restrict__ B,
                                                   int M, int K, int useExt) {
    const float* A = useExt ? Aext : (const float*)g_bufB;
    float* C = g_bufA;
    __shared__ float sA[2][128 * LDA];
    __shared__ float sB[2][16 * LDB];

    int tid = threadIdx.x;
    int wid = tid >> 5, lane = tid & 31;
    int g = lane >> 2, tg = lane & 3;
    int warp_m = wid >> 2;
    int warp_n = wid & 3;
    int block_row = blockIdx.x * 128;

    float acc[4][4][4];
    #pragma unroll
    for (int mi = 0; mi < 4; mi++)
        #pragma unroll
        for (int ni = 0; ni < 4; ni++)
            #pragma unroll
            for (int q = 0; q < 4; q++) acc[mi][ni][q] = 0.f;

    int nsteps = (K + 15) >> 4;

    auto load_stage = [&](int s) {
        int buf = s & 1;
        int k0 = s << 4;
        #pragma unroll
        for (int q = 0; q < 2; q++) {
            int c = tid + q * 256;
            int r = c >> 2;
            int cq = (c & 3) << 2;
            int grow = block_row + r;
            if (grow >= M) grow = M - 1;
            int kc = k0 + cq;
            int bytes = (K - kc) * 4;
            bytes = bytes < 0 ? 0 : (bytes > 16 ? 16 : bytes);
            int kcc = kc > K - 4 ? K - 4 : kc;
            cp_async16(&sA[buf][r * LDA + cq], &A[(size_t)grow * K + kcc], bytes);
        }
        #pragma unroll
        for (int q = 0; q < 2; q++) {
            int c = tid + q * 256;
            int kk = c >> 5;
            int c0 = (c & 31) << 2;
            int gk = k0 + kk;
            int bytes = gk < K ? 16 : 0;
            if (gk > K - 1) gk = K - 1;
            cp_async16(&sB[buf][kk * LDB + c0], &B[(size_t)gk * 128 + c0], bytes);
        }
    };

    load_stage(0);
    asm volatile("cp.async.commit_group;\n");

    for (int s = 0; s < nsteps; s++) {
        asm volatile("cp.async.wait_group 0;\n");
        __syncthreads();
        // Issue next stage AFTER the barrier: its writes (to buf (s+1)&1, last
        // read in iteration s-1) are ordered after all prior reads.
        if (s + 1 < nsteps) {
            load_stage(s + 1);
            asm volatile("cp.async.commit_group;\n");
        }

        int buf = s & 1;
        const float* Ar = sA[buf];
        const float* Br = sB[buf];

        uint32_t ah[4][4], al[4][4], bh[4][2], bl[4][2];
        #pragma unroll
        for (int mi = 0; mi < 4; mi++) {
            int r0 = warp_m * 64 + mi * 16 + g;
            float2 p0 = *(const float2*)&Ar[r0 * LDA + 2 * tg];
            float2 p1 = *(const float2*)&Ar[(r0 + 8) * LDA + 2 * tg];
            float2 p2 = *(const float2*)&Ar[r0 * LDA + 2 * tg + 8];
            float2 p3 = *(const float2*)&Ar[(r0 + 8) * LDA + 2 * tg + 8];
            split_pack(p0.x, p0.y, ah[mi][0], al[mi][0]);
            split_pack(p1.x, p1.y, ah[mi][1], al[mi][1]);
            split_pack(p2.x, p2.y, ah[mi][2], al[mi][2]);
            split_pack(p3.x, p3.y, ah[mi][3], al[mi][3]);
        }
        #pragma unroll
        for (int ni = 0; ni < 4; ni++) {
            int col = warp_n * 32 + ni * 8 + g;
            split_pack(Br[(2 * tg) * LDB + col], Br[(2 * tg + 1) * LDB + col],
                       bh[ni][0], bl[ni][0]);
            split_pack(Br[(2 * tg + 8) * LDB + col], Br[(2 * tg + 9) * LDB + col],
                       bh[ni][1], bl[ni][1]);
        }
        #pragma unroll
        for (int mi = 0; mi < 4; mi++)
            #pragma unroll
            for (int ni = 0; ni < 4; ni++) {
                mma16816(acc[mi][ni], ah[mi], bh[ni]);
                mma16816(acc[mi][ni], ah[mi], bl[ni]);
                mma16816(acc[mi][ni], al[mi], bh[ni]);
            }
    }

    #pragma unroll
    for (int mi = 0; mi < 4; mi++) {
        #pragma unroll
        for (int ni = 0; ni < 4; ni++) {
            int row = block_row + warp_m * 64 + mi * 16 + g;
            int col = warp_n * 32 + ni * 8 + 2 * tg;
            if (row < M)
                *(float2*)&C[(size_t)row * 128 + col] = make_float2(acc[mi][ni][0], acc[mi][ni][1]);
            if (row + 8 < M)
                *(float2*)&C[(size_t)(row + 8) * 128 + col] = make_float2(acc[mi][ni][2], acc[mi][ni][3]);
        }
    }
}

// ---------------- SGEMM: g_zraw[M,16] = g_bufB[M,128] * W[128,16] ----------------
__global__ __launch_bounds__(256) void sgemm16(const float* __restrict__ W, int M) {
    const float* A = g_bufB;
    float* C = g_zraw;
    __shared__ float Ws[128][16];
    __shared__ float xs[16][128];
    int tid = threadIdx.x;
    {
        int base = tid * 8;
        #pragma unroll
        for (int q = 0; q < 2; q++) {
            float4 v = *(const float4*)&W[base + q * 4];
            int o = base + q * 4;
            Ws[(o + 0) >> 4][(o + 0) & 15] = v.x;
            Ws[(o + 1) >> 4][(o + 1) & 15] = v.y;
            Ws[(o + 2) >> 4][(o + 2) & 15] = v.z;
            Ws[(o + 3) >> 4][(o + 3) & 15] = v.w;
        }
    }
    int row0 = blockIdx.x * 16;
    {
        #pragma unroll
        for (int q = 0; q < 2; q++) {
            int idx = tid * 2 + q;
            int r = idx >> 5;
            int c4 = (idx & 31) * 4;
            float4 v = make_float4(0.f, 0.f, 0.f, 0.f);
            if (row0 + r < M) v = *(const float4*)&A[(size_t)(row0 + r) * 128 + c4];
            *(float4*)&xs[r][c4] = v;
        }
    }
    __syncthreads();
    int r = tid >> 4;
    int c = tid & 15;
    float acc = 0.f;
    #pragma unroll 8
    for (int k = 0; k < 128; k++) acc += xs[r][k] * Ws[k][c];
    int row = row0 + r;
    if (row < M) C[(size_t)row * 16 + c] = acc;
}

// ---------------- per-node attention coefficients ----------------
__global__ void compute_al(const float* __restrict__ asrc,
                           const float* __restrict__ adst, int n, int H, int which) {
    int idx = blockIdx.x * blockDim.x + threadIdx.x;
    if (idx >= n * H) return;
    int head = idx % H;
    int node = idx / H;
    const float* h = (which == 0) ? (const float*)g_bufA : (const float*)g_zraw;
    const float* hp = h + (size_t)node * H * 16 + head * 16;
    const float* as = asrc + head * 16;
    const float* ad = adst + head * 16;
    float s = 0.f, d = 0.f;
    #pragma unroll
    for (int c = 0; c < 16; c++) {
        float v = hp[c];
        s += v * as[c];
        d += v * ad[c];
    }
    g_als[idx] = s;
    g_ald[idx] = d;
}

// ---------------- fused softmax + aggregate + bias + ELU, C=128 H=8 ----------------
// One warp per node, 256 threads, no smem. Max-free softmax.
// Pass A: denom gather. Pass B: weighted aggregate (simple loop — proven fastest).
__global__ __launch_bounds__(256) void gat_agg128(const float* __restrict__ bias, int n) {
    const float* h = g_bufA;
    float* out = g_bufB;
    int warp = (blockIdx.x * blockDim.x + threadIdx.x) >> 5;
    int lane = threadIdx.x & 31;
    if (warp >= n) return;
    int start = g_rowptr[warp];
    int end = g_rowptr[warp + 1];
    int myhead = lane >> 2;

    float4 a0 = *(const float4*)&g_ald[warp * 8];
    float4 a1 = *(const float4*)&g_ald[warp * 8 + 4];
    float aldv[8] = {a0.x, a0.y, a0.z, a0.w, a1.x, a1.y, a1.z, a1.w};

    // ---- pass A: per-head denominator (plain exp, no max) ----
    float dsum[8];
    #pragma unroll
    for (int i = 0; i < 8; i++) dsum[i] = 0.f;
    for (int e = start + lane; e < end; e += 32) {
        int s = g_colsrc[e];
        float4 s0 = *(const float4*)&g_als[s * 8];
        float4 s1 = *(const float4*)&g_als[s * 8 + 4];
        float lg[8] = {s0.x + aldv[0], s0.y + aldv[1], s0.z + aldv[2], s0.w + aldv[3],
                       s1.x + aldv[4], s1.y + aldv[5], s1.z + aldv[6], s1.w + aldv[7]};
        #pragma unroll
        for (int hh = 0; hh < 8; hh++) {
            float l = lg[hh];
            l = l > 0.f ? l : 0.2f * l;
            dsum[hh] += __expf(l);
        }
    }
    #pragma unroll
    for (int hh = 0; hh < 8; hh++)
        #pragma unroll
        for (int off = 16; off > 0; off >>= 1)
            dsum[hh] += __shfl_xor_sync(0xffffffffu, dsum[hh], off);

    float invd = 1.0f / (dsum[myhead] + 1e-16f);
    float aldh = aldv[myhead];

    // ---- pass B: weighted aggregation ----
    float4 acc = make_float4(0.f, 0.f, 0.f, 0.f);
    for (int e = start; e < end; e++) {
        int s = g_colsrc[e];
        float l = g_als[s * 8 + myhead] + aldh;
        l = l > 0.f ? l : 0.2f * l;
        float alpha = __expf(l) * invd;
        float4 v = *(const float4*)&h[(size_t)s * 128 + lane * 4];
        acc.x += alpha * v.x;
        acc.y += alpha * v.y;
        acc.z += alpha * v.z;
        acc.w += alpha * v.w;
    }
    float4 bv = *(const float4*)&bias[lane * 4];
    float4 o;
    o.x = acc.x + bv.x;
    o.y = acc.y + bv.y;
    o.z = acc.z + bv.z;
    o.w = acc.w + bv.w;
    o.x = o.x > 0.f ? o.x : expm1f(o.x);
    o.y = o.y > 0.f ? o.y : expm1f(o.y);
    o.z = o.z > 0.f ? o.z : expm1f(o.z);
    o.w = o.w > 0.f ? o.w : expm1f(o.w);
    *(float4*)&out[(size_t)warp * 128 + lane * 4] = o;
}

// ---------------- fused softmax + aggregate + bias, C=16 H=1 (layer 2) ----------------
__global__ __launch_bounds__(256) void gat_agg16(const float* __restrict__ bias,
                                                 float* __restrict__ out, int n) {
    const float* h = g_zraw;
    int warp = (blockIdx.x * blockDim.x + threadIdx.x) >> 5;
    int lane = threadIdx.x & 31;
    if (warp >= n) return;
    int start = g_rowptr[warp];
    int end = g_rowptr[warp + 1];
    float aldv = g_ald[warp];

    float dsum = 0.f;
    for (int e = start + lane; e < end; e += 32) {
        int s = g_colsrc[e];
        float l = g_als[s] + aldv;
        l = l > 0.f ? l : 0.2f * l;
        dsum += __expf(l);
    }
    #pragma unroll
    for (int off = 16; off > 0; off >>= 1)
        dsum += __shfl_xor_sync(0xffffffffu, dsum, off);
    float invd = 1.0f / (dsum + 1e-16f);

    float acc = 0.f;
    for (int e = start; e < end; e++) {
        int s = g_colsrc[e];
        float l = g_als[s] + aldv;
        l = l > 0.f ? l : 0.2f * l;
        float alpha = __expf(l) * invd;
        if (lane < 16) acc += alpha * h[(size_t)s * 16 + lane];
    }
    if (lane < 16) out[(size_t)warp * 16 + lane] = acc + bias[lane];
}

// ---------------- host launch ----------------
extern "C" void kernel_launch(void* const* d_in, const int* in_sizes, int n_in,
                              void* d_out, int out_size) {
    const float* x = (const float*)d_in[0];
    const int* ei = (const int*)d_in[1];
    const float* W0 = (const float*)d_in[2];
    const float* as0 = (const float*)d_in[3];
    const float* ad0 = (const float*)d_in[4];
    const float* b0 = (const float*)d_in[5];
    const float* W1 = (const float*)d_in[6];
    const float* as1 = (const float*)d_in[7];
    const float* ad1 = (const float*)d_in[8];
    const float* b1 = (const float*)d_in[9];
    const float* W2 = (const float*)d_in[10];
    const float* as2 = (const float*)d_in[11];
    const float* ad2 = (const float*)d_in[12];
    const float* b2 = (const float*)d_in[13];
    float* out = (float*)d_out;

    const int n = NN;
    const int E = EE;
    const int G = 1000;

    // CSR build interleaved with layer-0 GEMM (GEMM at launch index 3 — the
    // ncu capture slot — it depends only on x/W0; CSR ordering preserved).
    k_zero_deg<<<(n + 255) / 256, 256>>>(n);
    k_count<<<(E + 255) / 256, 256>>>(ei, E);
    int nb = (n + 1023) / 1024;
    k_scan1<<<nb, 1024>>>(n);
    mma_gemm128<<<(n + 127) / 128, 256>>>(x, W0, n, G, 1);   // layer-0 GEMM (index 3)
    k_scan2<<<1, 32>>>(nb);
    k_scan3<<<(n + 255) / 256, 256>>>(n, E);
    k_fill<<<(E + 255) / 256, 256>>>(ei, E);

    // layer 0 (GEMM already issued above)
    compute_al<<<(n * 8 + 255) / 256, 256>>>(as0, ad0, n, 8, 0);
    gat_agg128<<<(n * 32 + 255) / 256, 256>>>(b0, n);

    // layer 1
    mma_gemm128<<<(n + 127) / 128, 256>>>(nullptr, W1, n, 128, 0);
    compute_al<<<(n * 8 + 255) / 256, 256>>>(as1, ad1, n, 8, 0);
    gat_agg128<<<(n * 32 + 255) / 256, 256>>>(b1, n);

    // layer 2
    sgemm16<<<(n + 15) / 16, 256>>>(W2, n);
    compute_al<<<(n + 255) / 256, 256>>>(as2, ad2, n, 1, 1);
    gat_agg16<<<(n * 32 + 255) / 256, 256>>>(b2, out, n);
}